// round 14
// baseline (speedup 1.0000x reference)
#include <cuda_runtime.h>
#include <cuda_fp16.h>
#include <cstdint>

// Dilated banded attention: B=1, H=16, S=4096, D=64, r=2, window=128.
// R14: 32 q-rows per warp (two m16 A-tiles) -> each K/V ldmatrix feeds 4 MMAs,
// cutting smem read amplification ~44% (L1tex wavefronts were the cap).
// TQ=128, TB=128 (4 warps), 3 CTAs/SM. Pre-scaled Q, widened fill,
// lane-static masks, streaming 16-key chunks, ex2 MUFU, no max-subtraction.

namespace {
constexpr int H    = 16;
constexpr int S    = 4096;
constexpr int D    = 64;
constexpr int R    = 2;
constexpr int N    = S / R;      // 2048
constexpr int HALF = 64;
constexpr int TQ   = 128;        // 4 warps x 32 rows
constexpr int TB   = 128;        // threads per CTA
constexpr int TK   = TQ + 2 * HALF;  // 256 keys in smem

constexpr int KH_OFF = 0;            // 256*144 = 36864
constexpr int VH_OFF = 36864;
constexpr int SMEM_BYTES = 73728;    // 72 KB -> 3 CTAs/SM
}  // namespace

#define LDSM_X4(r0, r1, r2, r3, addr)                                                  \
    asm volatile("ldmatrix.sync.aligned.m8n8.x4.shared.b16 {%0,%1,%2,%3}, [%4];"       \
                 : "=r"(r0), "=r"(r1), "=r"(r2), "=r"(r3) : "r"(addr))
#define LDSM_X4T(r0, r1, r2, r3, addr)                                                 \
    asm volatile("ldmatrix.sync.aligned.m8n8.x4.trans.shared.b16 {%0,%1,%2,%3}, [%4];" \
                 : "=r"(r0), "=r"(r1), "=r"(r2), "=r"(r3) : "r"(addr))
#define MMA16816(c0, c1, c2, c3, a0, a1, a2, a3, b0, b1)                               \
    asm volatile("mma.sync.aligned.m16n8k16.row.col.f32.f16.f16.f32 "                  \
                 "{%0,%1,%2,%3}, {%4,%5,%6,%7}, {%8,%9}, {%0,%1,%2,%3};"               \
                 : "+f"(c0), "+f"(c1), "+f"(c2), "+f"(c3)                              \
                 : "r"(a0), "r"(a1), "r"(a2), "r"(a3), "r"(b0), "r"(b1))

__device__ __forceinline__ float ex2(float x) {
    float r;
    asm("ex2.approx.ftz.f32 %0, %1;" : "=f"(r) : "f"(x));
    return r;
}
__device__ __forceinline__ float frcp(float x) {
    float r;
    asm("rcp.approx.ftz.f32 %0, %1;" : "=f"(r) : "f"(x));
    return r;
}
__device__ __forceinline__ uint32_t packh2(float lo, float hi) {
    uint32_t r;
    asm("cvt.rn.f16x2.f32 %0, %1, %2;" : "=r"(r) : "f"(hi), "f"(lo));
    return r;
}
__device__ __forceinline__ void sts_h8(char* base, int boff, float4 a, float4 b) {
    uint4 v;
    asm("cvt.rn.f16x2.f32 %0, %1, %2;" : "=r"(v.x) : "f"(a.y), "f"(a.x));
    asm("cvt.rn.f16x2.f32 %0, %1, %2;" : "=r"(v.y) : "f"(a.w), "f"(a.z));
    asm("cvt.rn.f16x2.f32 %0, %1, %2;" : "=r"(v.z) : "f"(b.y), "f"(b.x));
    asm("cvt.rn.f16x2.f32 %0, %1, %2;" : "=r"(v.w) : "f"(b.w), "f"(b.z));
    *reinterpret_cast<uint4*>(base + boff) = v;
}

__global__ __launch_bounds__(TB, 3)
void dilated_attn_r14(const float* __restrict__ gq,
                      const float* __restrict__ gk,
                      const float* __restrict__ gv,
                      float* __restrict__ gout) {
    extern __shared__ char smem[];
    const uint32_t sbase = (uint32_t)__cvta_generic_to_shared(smem);

    const int h     = blockIdx.z;
    const int off   = blockIdx.y;
    const int i0    = blockIdx.x * TQ;
    const int kbase = i0 - HALF;
    const int tid   = threadIdx.x;
    const int lane  = tid & 31;
    const int w     = tid >> 5;        // 0..3, owns rows [32w, 32w+32)
    const int g     = lane >> 2;
    const int qd    = lane & 3;

    const float* qh = gq + (size_t)h * S * D;
    const float* kh = gk + (size_t)h * S * D;
    const float* vh = gv + (size_t)h * S * D;
    float*       oh = gout + (size_t)h * S * D;

    const float kscale = 0.125f * 1.44269504f;

    // ---- Q A-fragments for two m16 tiles, direct from gmem, pre-scaled ----
    const int qr0 = 32 * w;
    const int rA = qr0 + g, rB = rA + 8, rC = rA + 16, rD = rA + 24;
    const float* qpA = qh + (size_t)(2 * (i0 + rA) + off) * D;
    const float* qpB = qh + (size_t)(2 * (i0 + rB) + off) * D;
    const float* qpC = qh + (size_t)(2 * (i0 + rC) + off) * D;
    const float* qpD = qh + (size_t)(2 * (i0 + rD) + off) * D;
    uint32_t qa0[4][4], qa1[4][4];
#pragma unroll
    for (int ks = 0; ks < 4; ++ks) {
        float2 a0 = *reinterpret_cast<const float2*>(qpA + ks * 16 + 2 * qd);
        float2 b0 = *reinterpret_cast<const float2*>(qpB + ks * 16 + 2 * qd);
        float2 a1 = *reinterpret_cast<const float2*>(qpA + ks * 16 + 8 + 2 * qd);
        float2 b1 = *reinterpret_cast<const float2*>(qpB + ks * 16 + 8 + 2 * qd);
        qa0[ks][0] = packh2(kscale * a0.x, kscale * a0.y);
        qa0[ks][1] = packh2(kscale * b0.x, kscale * b0.y);
        qa0[ks][2] = packh2(kscale * a1.x, kscale * a1.y);
        qa0[ks][3] = packh2(kscale * b1.x, kscale * b1.y);
        float2 c0_ = *reinterpret_cast<const float2*>(qpC + ks * 16 + 2 * qd);
        float2 d0_ = *reinterpret_cast<const float2*>(qpD + ks * 16 + 2 * qd);
        float2 c1_ = *reinterpret_cast<const float2*>(qpC + ks * 16 + 8 + 2 * qd);
        float2 d1_ = *reinterpret_cast<const float2*>(qpD + ks * 16 + 8 + 2 * qd);
        qa1[ks][0] = packh2(kscale * c0_.x, kscale * c0_.y);
        qa1[ks][1] = packh2(kscale * d0_.x, kscale * d0_.y);
        qa1[ks][2] = packh2(kscale * c1_.x, kscale * c1_.y);
        qa1[ks][3] = packh2(kscale * d1_.x, kscale * d1_.y);
    }

    // ---- K/V fill: 8-float granularity (16 iters with 128 threads) ----
    const bool edge = (blockIdx.x == 0) || (blockIdx.x == gridDim.x - 1);
    if (!edge) {
        for (int it = 0; it < (TK * 8) / TB; ++it) {
            int idx = tid + it * TB;
            int row = idx >> 3, c8 = (idx & 7) << 3;
            size_t gb = (size_t)(2 * (kbase + row) + off) * D + c8;
            float4 k0 = *reinterpret_cast<const float4*>(kh + gb);
            float4 k1 = *reinterpret_cast<const float4*>(kh + gb + 4);
            float4 v0 = *reinterpret_cast<const float4*>(vh + gb);
            float4 v1 = *reinterpret_cast<const float4*>(vh + gb + 4);
            int boff = row * 144 + c8 * 2;
            sts_h8(smem + KH_OFF, boff, k0, k1);
            sts_h8(smem + VH_OFF, boff, v0, v1);
        }
    } else {
        for (int it = 0; it < (TK * 8) / TB; ++it) {
            int idx = tid + it * TB;
            int row = idx >> 3, c8 = (idx & 7) << 3;
            int j = kbase + row;
            float4 k0 = make_float4(0.f, 0.f, 0.f, 0.f), k1 = k0, v0 = k0, v1 = k0;
            if (j >= 0 && j < N) {
                size_t gb = (size_t)(2 * j + off) * D + c8;
                k0 = *reinterpret_cast<const float4*>(kh + gb);
                k1 = *reinterpret_cast<const float4*>(kh + gb + 4);
                v0 = *reinterpret_cast<const float4*>(vh + gb);
                v1 = *reinterpret_cast<const float4*>(vh + gb + 4);
            }
            int boff = row * 144 + c8 * 2;
            sts_h8(smem + KH_OFF, boff, k0, k1);
            sts_h8(smem + VH_OFF, boff, v0, v1);
        }
    }
    __syncthreads();  // the ONLY barrier

    const int ktw = 4 * w;  // warp's first tile (20 tiles: ktw..ktw+19)
    const uint32_t kB4 = sbase + KH_OFF
                       + (ktw * 8 + (lane & 7) + ((lane & 16) ? 8 : 0)) * 144
                       + ((lane & 8) ? 16 : 0);
    const uint32_t vB4 = sbase + VH_OFF + (ktw * 8 + (lane & 15)) * 144
                       + ((lane & 16) ? 16 : 0);

    const int t0 = 2 * qd, t1 = 2 * qd + 1;
    const float NEG = -1e30f;
    const float bge0 = (t0 >= g) ? 0.f : NEG;
    const float bge1 = (t1 >= g) ? 0.f : NEG;
    const float ble0 = (t0 <= g) ? 0.f : NEG;
    const float ble1 = (t1 <= g) ? 0.f : NEG;

    float o0[8][4], o1[8][4];
#pragma unroll
    for (int n = 0; n < 8; ++n)
#pragma unroll
        for (int e = 0; e < 4; ++e) { o0[n][e] = 0.f; o1[n][e] = 0.f; }
    float s0l = 0.f, s0h = 0.f, s1l = 0.f, s1h = 0.f;

    // ================= 10 streamed chunks of 16 keys =================
#pragma unroll
    for (int kc = 0; kc < 10; ++kc) {
        float c0[4] = {0.f, 0.f, 0.f, 0.f};   // m0 x tile 2kc
        float c1[4] = {0.f, 0.f, 0.f, 0.f};   // m0 x tile 2kc+1
        float d0[4] = {0.f, 0.f, 0.f, 0.f};   // m1 x tile 2kc
        float d1[4] = {0.f, 0.f, 0.f, 0.f};   // m1 x tile 2kc+1
        const uint32_t kchunk = kB4 + kc * 16 * 144;
#pragma unroll
        for (int ks = 0; ks < 4; ++ks) {
            uint32_t b0, b1, b2, b3;
            LDSM_X4(b0, b1, b2, b3, kchunk + ks * 32);
            MMA16816(c0[0], c0[1], c0[2], c0[3],
                     qa0[ks][0], qa0[ks][1], qa0[ks][2], qa0[ks][3], b0, b1);
            MMA16816(c1[0], c1[1], c1[2], c1[3],
                     qa0[ks][0], qa0[ks][1], qa0[ks][2], qa0[ks][3], b2, b3);
            MMA16816(d0[0], d0[1], d0[2], d0[3],
                     qa1[ks][0], qa1[ks][1], qa1[ks][2], qa1[ks][3], b0, b1);
            MMA16816(d1[0], d1[1], d1[2], d1[3],
                     qa1[ks][0], qa1[ks][1], qa1[ks][2], qa1[ks][3], b2, b3);
        }

        // ---- mask + ex2: warp-local tile indices nt0=2kc, nt1=2kc+1 ----
        float E0[4], E1[4], F0[4], F1[4];
        if (!edge) {
            if (kc == 0) {
                E0[0] = ex2(c0[0] + bge0); E0[1] = ex2(c0[1] + bge1);
                E0[2] = 0.f;               E0[3] = 0.f;
                E1[0] = ex2(c1[0]);        E1[1] = ex2(c1[1]);
                E1[2] = ex2(c1[2] + bge0); E1[3] = ex2(c1[3] + bge1);
                F0[0] = F0[1] = F0[2] = F0[3] = 0.f;
                F1[0] = F1[1] = F1[2] = F1[3] = 0.f;
            } else if (kc == 1) {
                E0[0] = ex2(c0[0]); E0[1] = ex2(c0[1]); E0[2] = ex2(c0[2]); E0[3] = ex2(c0[3]);
                E1[0] = ex2(c1[0]); E1[1] = ex2(c1[1]); E1[2] = ex2(c1[2]); E1[3] = ex2(c1[3]);
                F0[0] = ex2(d0[0] + bge0); F0[1] = ex2(d0[1] + bge1);
                F0[2] = 0.f;               F0[3] = 0.f;
                F1[0] = ex2(d1[0]);        F1[1] = ex2(d1[1]);
                F1[2] = ex2(d1[2] + bge0); F1[3] = ex2(d1[3] + bge1);
            } else if (kc == 8) {
                E0[0] = ex2(c0[0] + ble0); E0[1] = ex2(c0[1] + ble1);
                E0[2] = ex2(c0[2]);        E0[3] = ex2(c0[3]);
                E1[0] = 0.f;               E1[1] = 0.f;
                E1[2] = ex2(c1[2] + ble0); E1[3] = ex2(c1[3] + ble1);
                F0[0] = ex2(d0[0]); F0[1] = ex2(d0[1]); F0[2] = ex2(d0[2]); F0[3] = ex2(d0[3]);
                F1[0] = ex2(d1[0]); F1[1] = ex2(d1[1]); F1[2] = ex2(d1[2]); F1[3] = ex2(d1[3]);
            } else if (kc == 9) {
                E0[0] = E0[1] = E0[2] = E0[3] = 0.f;
                E1[0] = E1[1] = E1[2] = E1[3] = 0.f;
                F0[0] = ex2(d0[0] + ble0); F0[1] = ex2(d0[1] + ble1);
                F0[2] = ex2(d0[2]);        F0[3] = ex2(d0[3]);
                F1[0] = 0.f;               F1[1] = 0.f;
                F1[2] = ex2(d1[2] + ble0); F1[3] = ex2(d1[3] + ble1);
            } else {  // interior chunks 2..7: no mask at all
                E0[0] = ex2(c0[0]); E0[1] = ex2(c0[1]); E0[2] = ex2(c0[2]); E0[3] = ex2(c0[3]);
                E1[0] = ex2(c1[0]); E1[1] = ex2(c1[1]); E1[2] = ex2(c1[2]); E1[3] = ex2(c1[3]);
                F0[0] = ex2(d0[0]); F0[1] = ex2(d0[1]); F0[2] = ex2(d0[2]); F0[3] = ex2(d0[3]);
                F1[0] = ex2(d1[0]); F1[1] = ex2(d1[1]); F1[2] = ex2(d1[2]); F1[3] = ex2(d1[3]);
            }
        } else {
            // Generic path (first/last q-block): band + sequence-edge checks.
#pragma unroll
            for (int mi = 0; mi < 2; ++mi) {
#pragma unroll
                for (int ni = 0; ni < 2; ++ni) {
                    const float* cc = (mi == 0) ? (ni ? c1 : c0) : (ni ? d1 : d0);
                    float* EE = (mi == 0) ? (ni ? E1 : E0) : (ni ? F1 : F0);
                    int rlo = qr0 + mi * 16 + g;
#pragma unroll
                    for (int e = 0; e < 2; ++e) {
                        int keyl = (ktw + 2 * kc + ni) * 8 + 2 * qd + e;
                        bool inb = (unsigned)(kbase + keyl) < (unsigned)N;
                        bool vlo = inb && (unsigned)(keyl - rlo) <= 2u * HALF;
                        bool vhi = inb && (unsigned)(keyl - (rlo + 8)) <= 2u * HALF;
                        EE[e]     = vlo ? ex2(cc[e]) : 0.f;
                        EE[2 + e] = vhi ? ex2(cc[2 + e]) : 0.f;
                    }
                }
            }
        }
        s0l += E0[0] + E0[1] + E1[0] + E1[1];
        s0h += E0[2] + E0[3] + E1[2] + E1[3];
        s1l += F0[0] + F0[1] + F1[0] + F1[1];
        s1h += F0[2] + F0[3] + F1[2] + F1[3];
        uint32_t p00 = packh2(E0[0], E0[1]);
        uint32_t p01 = packh2(E0[2], E0[3]);
        uint32_t p02 = packh2(E1[0], E1[1]);
        uint32_t p03 = packh2(E1[2], E1[3]);
        uint32_t p10 = packh2(F0[0], F0[1]);
        uint32_t p11 = packh2(F0[2], F0[3]);
        uint32_t p12 = packh2(F1[0], F1[1]);
        uint32_t p13 = packh2(F1[2], F1[3]);

        // ---- PV: one V ldmatrix pair feeds BOTH m-tiles ----
        const uint32_t vchunk = vB4 + kc * 16 * 144;
#pragma unroll
        for (int dtp = 0; dtp < 4; ++dtp) {
            uint32_t b0, b1, b2, b3;
            LDSM_X4T(b0, b1, b2, b3, vchunk + dtp * 32);
            int n0 = 2 * dtp, n1 = 2 * dtp + 1;
            MMA16816(o0[n0][0], o0[n0][1], o0[n0][2], o0[n0][3], p00, p01, p02, p03, b0, b1);
            MMA16816(o0[n1][0], o0[n1][1], o0[n1][2], o0[n1][3], p00, p01, p02, p03, b2, b3);
            MMA16816(o1[n0][0], o1[n0][1], o1[n0][2], o1[n0][3], p10, p11, p12, p13, b0, b1);
            MMA16816(o1[n1][0], o1[n1][1], o1[n1][2], o1[n1][3], p10, p11, p12, p13, b2, b3);
        }
    }

    // ================= row sums + normalize + store (4 rows/thread) =================
    s0l += __shfl_xor_sync(0xffffffffu, s0l, 1);
    s0l += __shfl_xor_sync(0xffffffffu, s0l, 2);
    s0h += __shfl_xor_sync(0xffffffffu, s0h, 1);
    s0h += __shfl_xor_sync(0xffffffffu, s0h, 2);
    s1l += __shfl_xor_sync(0xffffffffu, s1l, 1);
    s1l += __shfl_xor_sync(0xffffffffu, s1l, 2);
    s1h += __shfl_xor_sync(0xffffffffu, s1h, 1);
    s1h += __shfl_xor_sync(0xffffffffu, s1h, 2);
    const float iA = frcp(s0l), iB = frcp(s0h), iC = frcp(s1l), iD = frcp(s1h);
    const int gsA = 2 * (i0 + rA) + off;
    const int gsB = 2 * (i0 + rB) + off;
    const int gsC = 2 * (i0 + rC) + off;
    const int gsD = 2 * (i0 + rD) + off;
#pragma unroll
    for (int dt = 0; dt < 8; ++dt) {
        int col = dt * 8 + 2 * qd;
        *reinterpret_cast<float2*>(oh + (size_t)gsA * D + col) =
            make_float2(o0[dt][0] * iA, o0[dt][1] * iA);
        *reinterpret_cast<float2*>(oh + (size_t)gsB * D + col) =
            make_float2(o0[dt][2] * iB, o0[dt][3] * iB);
        *reinterpret_cast<float2*>(oh + (size_t)gsC * D + col) =
            make_float2(o1[dt][0] * iC, o1[dt][1] * iC);
        *reinterpret_cast<float2*>(oh + (size_t)gsD * D + col) =
            make_float2(o1[dt][2] * iD, o1[dt][3] * iD);
    }
}

extern "C" void kernel_launch(void* const* d_in, const int* in_sizes, int n_in,
                              void* d_out, int out_size) {
    (void)in_sizes; (void)n_in; (void)out_size;
    const float* q = (const float*)d_in[0];
    const float* k = (const float*)d_in[1];
    const float* v = (const float*)d_in[2];
    float* out = (float*)d_out;

    static bool attr_done = false;
    if (!attr_done) {
        (void)cudaFuncSetAttribute(dilated_attn_r14,
                                   cudaFuncAttributeMaxDynamicSharedMemorySize, SMEM_BYTES);
        attr_done = true;
    }
    dim3 grid(N / TQ, R, H);  // (16, 2, 16) = 512 CTAs
    dilated_attn_r14<<<grid, TB, SMEM_BYTES>>>(q, k, v, out);
}